// round 3
// baseline (speedup 1.0000x reference)
#include <cuda_runtime.h>

#define N_NODES 100000
#define N_FEAT  48
#define N_EFEAT 16
#define TOT     112     // 2*N_FEAT + N_EFEAT
#define HID     128
#define ETILE   128
#define KC      16
#define LDA     116     // A tile row stride (floats), 16B-aligned rows
#define LDH     132     // H tile row stride (floats), 16B-aligned rows

// Scratch (allocation-free rule: __device__ globals)
__device__ float g_msum[N_NODES * N_FEAT];   // 19.2 MB message accumulator
__device__ int   g_cnt[N_NODES];             // in-degree counts

// ---------------- zero scratch (runs every replay) ----------------
__global__ void zero_kernel() {
    int stride = gridDim.x * blockDim.x;
    for (int i = blockIdx.x * blockDim.x + threadIdx.x; i < N_NODES * N_FEAT; i += stride)
        g_msum[i] = 0.f;
    for (int i = blockIdx.x * blockDim.x + threadIdx.x; i < N_NODES; i += stride)
        g_cnt[i] = 0;
}

// ---------------- fused GEMM + bias + ReLU: [128 x K] @ [K x 128] ----------------
// Thread grid 16x16, each thread 8 rows x 8 cols.
__device__ __forceinline__ void gemm_relu_128(
    const float* __restrict__ Ain, int lda, int K,
    const float* __restrict__ Wg, const float* __restrict__ bg,
    float* __restrict__ Hout,
    float* __restrict__ Wc, int tid)
{
    const int tx = tid & 15, ty = tid >> 4;
    const int r0 = ty * 8, c0 = tx * 8;
    float acc[8][8];
#pragma unroll
    for (int i = 0; i < 8; i++)
#pragma unroll
        for (int j = 0; j < 8; j++) acc[i][j] = 0.f;

    for (int kc = 0; kc < K; kc += KC) {
        __syncthreads();   // protect Wc reuse + (first iter) upstream smem writes
        {   // stage 16x128 weight chunk: 8 contiguous floats per thread
            int r = tid >> 4;
            int c = (tid & 15) * 8;
            const float4* s = reinterpret_cast<const float4*>(Wg + (kc + r) * HID + c);
            float4 v0 = s[0], v1 = s[1];
            float4* d = reinterpret_cast<float4*>(Wc + r * HID + c);
            d[0] = v0; d[1] = v1;
        }
        __syncthreads();
#pragma unroll
        for (int kk = 0; kk < KC; kk++) {
            const float4* wr = reinterpret_cast<const float4*>(Wc + kk * HID + c0);
            float4 w0 = wr[0], w1 = wr[1];
            float w[8] = {w0.x, w0.y, w0.z, w0.w, w1.x, w1.y, w1.z, w1.w};
#pragma unroll
            for (int i = 0; i < 8; i++) {
                float a = Ain[(r0 + i) * lda + kc + kk];
#pragma unroll
                for (int j = 0; j < 8; j++)
                    acc[i][j] = fmaf(a, w[j], acc[i][j]);
            }
        }
    }
    // epilogue: bias + ReLU -> Hout
#pragma unroll
    for (int j = 0; j < 8; j++) {
        int c = c0 + j;
        float b = bg[c];
#pragma unroll
        for (int i = 0; i < 8; i++) {
            Hout[(r0 + i) * LDH + c] = fmaxf(acc[i][j] + b, 0.f);
        }
    }
}

// ---------------- final GEMM: [128 x 128] @ [128 x 48], bias, atomic scatter ----------------
// Thread grid 32x8, each thread 4 rows x 6 cols.
__device__ __forceinline__ void gemm_out48(
    const float* __restrict__ Ain,           // H2, stride LDH, K = HID
    const float* __restrict__ Wg,            // [128][48]
    const float* __restrict__ bg,            // [48]
    const int* __restrict__ sTgt,
    float* __restrict__ Wc, int tid)
{
    const int cg = tid & 7, rg = tid >> 3;
    const int r0 = rg * 4, c0 = cg * 6;
    float acc[4][6];
#pragma unroll
    for (int i = 0; i < 4; i++)
#pragma unroll
        for (int j = 0; j < 6; j++) acc[i][j] = 0.f;

    for (int kc = 0; kc < HID; kc += KC) {
        __syncthreads();
        for (int i = tid; i < KC * N_FEAT; i += 256) {
            int r = i / N_FEAT, c = i - r * N_FEAT;
            Wc[i] = Wg[(kc + r) * N_FEAT + c];
        }
        __syncthreads();
#pragma unroll
        for (int kk = 0; kk < KC; kk++) {
            float w[6];
#pragma unroll
            for (int j = 0; j < 6; j++) w[j] = Wc[kk * N_FEAT + c0 + j];
#pragma unroll
            for (int i = 0; i < 4; i++) {
                float a = Ain[(r0 + i) * LDH + kc + kk];
#pragma unroll
                for (int j = 0; j < 6; j++)
                    acc[i][j] = fmaf(a, w[j], acc[i][j]);
            }
        }
    }
#pragma unroll
    for (int i = 0; i < 4; i++) {
        int tgt = sTgt[r0 + i];
        if (tgt < 0 || tgt >= N_NODES) continue;   // defensive: never atomic out of range
        float* dst = g_msum + (size_t)tgt * N_FEAT;
#pragma unroll
        for (int j = 0; j < 6; j++) {
            int c = c0 + j;
            atomicAdd(dst + c, acc[i][j] + bg[c]);
        }
    }
}

// ---------------- main fused kernel: one CTA per 128 edges ----------------
__global__ void __launch_bounds__(256, 1) main_kernel(
    const float* __restrict__ x,
    const int* __restrict__ ei,              // int32! (JAX default: x64 disabled)
    const float* __restrict__ efeat,
    const float* __restrict__ W1, const float* __restrict__ b1,
    const float* __restrict__ W2, const float* __restrict__ b2,
    const float* __restrict__ W3, const float* __restrict__ b3,
    int E)
{
    extern __shared__ float smem[];
    float* bufA = smem;                   // 128*132 floats: A-tile (lda=116), later H2 (ldh=132)
    float* bufH = bufA + ETILE * LDH;     // 128*132 floats: H1
    float* bufW = bufH + ETILE * LDH;     // 16*128 floats: staged W chunk
    int*   sSrc = (int*)(bufW + KC * HID);
    int*   sTgt = sSrc + ETILE;

    const int tid  = threadIdx.x;
    const int base = blockIdx.x * ETILE;

    // indices + degree counts
    if (tid < ETILE) {
        int e = base + tid;
        int s = 0, t = -1;
        if (e < E) {
            s = ei[e];          // row 0: source
            t = ei[E + e];      // row 1: target
            if ((unsigned)s >= (unsigned)N_NODES) s = 0;   // defensive
            if ((unsigned)t >= (unsigned)N_NODES) t = -1;  // defensive
            if (t >= 0) atomicAdd(&g_cnt[t], 1);
        }
        sSrc[tid] = s;
        sTgt[tid] = t;
    }
    __syncthreads();

    // gather [x[src] | x[tgt] | edge_feat] -> A tile, 28 float4 per edge (cols c*4)
    for (int i = tid; i < ETILE * 28; i += 256) {
        int e = i / 28, c = i - (i / 28) * 28;
        float4 v = make_float4(0.f, 0.f, 0.f, 0.f);
        if (c < 12) {
            const float4* p = reinterpret_cast<const float4*>(x + (size_t)sSrc[e] * N_FEAT);
            v = p[c];
        } else if (c < 24) {
            int t = sTgt[e];
            if (t >= 0) {
                const float4* p = reinterpret_cast<const float4*>(x + (size_t)t * N_FEAT);
                v = p[c - 12];
            }
        } else {
            int eg = base + e;
            if (eg < E) {
                const float4* p = reinterpret_cast<const float4*>(efeat + (size_t)eg * N_EFEAT);
                v = p[c - 24];
            }
        }
        *reinterpret_cast<float4*>(bufA + e * LDA + c * 4) = v;
    }
    // gemm's first loop-top __syncthreads orders gather writes before reads

    gemm_relu_128(bufA, LDA, TOT, W1, b1, bufH, bufW, tid);   // H1 = relu(A @ W1 + b1)
    gemm_relu_128(bufH, LDH, HID, W2, b2, bufA, bufW, tid);   // H2 = relu(H1 @ W2 + b2)
    gemm_out48 (bufA, W3, b3, sTgt, bufW, tid);               // scatter(H2 @ W3 + b3)
}

// ---------------- finalize: out = x + msum / max(cnt, 1) ----------------
__global__ void finalize_kernel(const float* __restrict__ x, float* __restrict__ out) {
    int stride = gridDim.x * blockDim.x;
    for (int i = blockIdx.x * blockDim.x + threadIdx.x; i < N_NODES * N_FEAT; i += stride) {
        int node = i / N_FEAT;
        float cnt = (float)g_cnt[node];
        out[i] = x[i] + g_msum[i] / fmaxf(cnt, 1.f);
    }
}

extern "C" void kernel_launch(void* const* d_in, const int* in_sizes, int n_in,
                              void* d_out, int out_size) {
    const float* x  = (const float*)d_in[0];
    const int*   ei = (const int*)d_in[1];     // int32 edge_index
    const float* ef = (const float*)d_in[2];
    const float* W1 = (const float*)d_in[3];
    const float* b1 = (const float*)d_in[4];
    const float* W2 = (const float*)d_in[5];
    const float* b2 = (const float*)d_in[6];
    const float* W3 = (const float*)d_in[7];
    const float* b3 = (const float*)d_in[8];
    const int E = in_sizes[2] / N_EFEAT;

    const int smem_bytes = (ETILE * LDH * 2 + KC * HID) * 4 + 2 * ETILE * 4;
    cudaFuncSetAttribute(main_kernel, cudaFuncAttributeMaxDynamicSharedMemorySize, smem_bytes);

    zero_kernel<<<4096, 256>>>();
    main_kernel<<<(E + ETILE - 1) / ETILE, 256, smem_bytes>>>(
        x, ei, ef, W1, b1, W2, b2, W3, b3, E);
    finalize_kernel<<<4096, 256>>>(x, (float*)d_out);
}

// round 5
// speedup vs baseline: 2.4487x; 2.4487x over previous
#include <cuda_runtime.h>

typedef unsigned int u32;

#define N_NODES 100000
#define N_FEAT  48
#define N_EFEAT 16
#define TOT     112
#define HID     128
#define ETILE   64
#define NCTAS   148

#define LDB  132   // A/H buffer stride (words), ≡4 mod 32: frag loads conflict-free
#define LDW  136   // W1/W2 stride, ≡8 mod 32: B-frag loads conflict-free
#define LDW3 56    // W3 stride, ≡24 mod 32: B-frag loads conflict-free
#define LDD  52    // D3 staging stride

// smem word offsets
#define BUF0 0                    // 64*132 = 8448 : A tile / H2
#define BUF1 8448                 // 8448        : H1 / D3 staging
#define W1S  16896                // 112*136 = 15232
#define W2S  32128                // 128*136 = 17408
#define W3S  49536                // 128*56  = 7168
#define B1S  56704                // 128
#define B2S  56832                // 128
#define SRCS 56960                // 64
#define TGTS 57024                // 64
#define SMEM_WORDS 57088          // 228,352 bytes

__device__ float g_msum[N_NODES * N_FEAT];
__device__ int   g_cnt[N_NODES];

__device__ __forceinline__ u32 f2tf32(float f) {
    u32 u; asm("cvt.rna.tf32.f32 %0, %1;" : "=r"(u) : "f"(f)); return u;
}
__device__ __forceinline__ void mma_tf32(float* d, const u32* a, const u32* b) {
    asm volatile("mma.sync.aligned.m16n8k8.row.col.f32.tf32.tf32.f32 "
        "{%0,%1,%2,%3}, {%4,%5,%6,%7}, {%8,%9}, {%0,%1,%2,%3};"
        : "+f"(d[0]), "+f"(d[1]), "+f"(d[2]), "+f"(d[3])
        : "r"(a[0]), "r"(a[1]), "r"(a[2]), "r"(a[3]), "r"(b[0]), "r"(b[1]));
}
__device__ __forceinline__ void red_v4(float* p, float x, float y, float z, float w) {
    asm volatile("red.global.add.v4.f32 [%0], {%1,%2,%3,%4};"
        :: "l"(p), "f"(x), "f"(y), "f"(z), "f"(w) : "memory");
}

__global__ void zero_kernel() {
    int stride = gridDim.x * blockDim.x;
    for (int i = blockIdx.x * blockDim.x + threadIdx.x; i < N_NODES * N_FEAT; i += stride)
        g_msum[i] = 0.f;
    for (int i = blockIdx.x * blockDim.x + threadIdx.x; i < N_NODES; i += stride)
        g_cnt[i] = 0;
}

// GEMM [64 x K] @ [K x 128] + bias + relu -> H (tf32). Warp wq: 32 rows x 32 cols.
__device__ __forceinline__ void gemm_hidden(
    const u32* __restrict__ A,      // [64][LDB] tf32
    const u32* __restrict__ W,      // [K][LDW] tf32
    int K,
    const float* __restrict__ bias, // [128]
    u32* __restrict__ H,            // [64][LDB] out tf32
    int lane, int wq)
{
    const int mb = (wq & 1) * 32, nb = (wq >> 1) * 32;
    const int r = lane >> 2, c = lane & 3;
    float acc[2][4][4] = {};
    for (int k = 0; k < K; k += 8) {
        u32 a[2][4];
#pragma unroll
        for (int mi = 0; mi < 2; mi++) {
            const u32* ap = A + (mb + mi * 16 + r) * LDB + k + c;
            a[mi][0] = ap[0];
            a[mi][1] = ap[8 * LDB];
            a[mi][2] = ap[4];
            a[mi][3] = ap[8 * LDB + 4];
        }
#pragma unroll
        for (int ni = 0; ni < 4; ni++) {
            const u32* bp = W + (k + c) * LDW + nb + ni * 8 + r;
            u32 b[2] = { bp[0], bp[4 * LDW] };
#pragma unroll
            for (int mi = 0; mi < 2; mi++)
                mma_tf32(acc[mi][ni], a[mi], b);
        }
    }
#pragma unroll
    for (int mi = 0; mi < 2; mi++) {
        int r0 = mb + mi * 16 + r;
#pragma unroll
        for (int ni = 0; ni < 4; ni++) {
            int col = nb + ni * 8 + 2 * c;
            float blo = bias[col], bhi = bias[col + 1];
            u32 lo = f2tf32(fmaxf(acc[mi][ni][0] + blo, 0.f));
            u32 hi = f2tf32(fmaxf(acc[mi][ni][1] + bhi, 0.f));
            *reinterpret_cast<uint2*>(H + r0 * LDB + col) = make_uint2(lo, hi);
            lo = f2tf32(fmaxf(acc[mi][ni][2] + blo, 0.f));
            hi = f2tf32(fmaxf(acc[mi][ni][3] + bhi, 0.f));
            *reinterpret_cast<uint2*>(H + (r0 + 8) * LDB + col) = make_uint2(lo, hi);
        }
    }
}

__global__ void __launch_bounds__(256, 1) main_kernel(
    const float* __restrict__ x,
    const int* __restrict__ ei,
    const float* __restrict__ efeat,
    const float* __restrict__ W1, const float* __restrict__ b1,
    const float* __restrict__ W2, const float* __restrict__ b2,
    const float* __restrict__ W3,
    int E)
{
    extern __shared__ u32 sw[];
    float* sf = reinterpret_cast<float*>(sw);
    const int tid = threadIdx.x;
    const int lane = tid & 31, wq = tid >> 5;

    // ---- one-time: stage weights (tf32) + biases ----
    for (int idx = tid; idx < TOT * HID; idx += 256) {
        int k = idx >> 7, n = idx & 127;
        sw[W1S + k * LDW + n] = f2tf32(W1[idx]);
    }
    for (int idx = tid; idx < HID * HID; idx += 256) {
        int k = idx >> 7, n = idx & 127;
        sw[W2S + k * LDW + n] = f2tf32(W2[idx]);
    }
    for (int idx = tid; idx < HID * N_FEAT; idx += 256) {
        int k = idx / N_FEAT, n = idx - k * N_FEAT;
        sw[W3S + k * LDW3 + n] = f2tf32(W3[idx]);
    }
    if (tid < HID) {
        sf[B1S + tid] = b1[tid];
        sf[B2S + tid] = b2[tid];
    }

    int* sSrc = reinterpret_cast<int*>(sw + SRCS);
    int* sTgt = reinterpret_cast<int*>(sw + TGTS);
    const int num_tiles = (E + ETILE - 1) / ETILE;

    for (int tile = blockIdx.x; tile < num_tiles; tile += gridDim.x) {
        __syncthreads();                         // buf0/buf1 free to overwrite
        const int base = tile * ETILE;
        if (tid < ETILE) {
            int e = base + tid, s = 0, t = -1;
            if (e < E) {
                s = ei[e]; t = ei[E + e];
                if ((u32)s >= (u32)N_NODES) s = 0;
                if ((u32)t >= (u32)N_NODES) t = -1;
                if (t >= 0) atomicAdd(&g_cnt[t], 1);
            }
            sSrc[tid] = s; sTgt[tid] = t;
        }
        __syncthreads();

        // ---- gather [x[src] | x[tgt] | ef] -> buf0 (tf32), 64 edges x 28 float4 ----
        for (int i = tid; i < ETILE * 28; i += 256) {
            int e = i / 28, q = i - (i / 28) * 28;
            float4 v = make_float4(0.f, 0.f, 0.f, 0.f);
            if (q < 12) {
                v = reinterpret_cast<const float4*>(x + (size_t)sSrc[e] * N_FEAT)[q];
            } else if (q < 24) {
                int t = sTgt[e];
                if (t >= 0) v = reinterpret_cast<const float4*>(x + (size_t)t * N_FEAT)[q - 12];
            } else if (base + e < E) {
                v = reinterpret_cast<const float4*>(efeat + (size_t)(base + e) * N_EFEAT)[q - 24];
            }
            uint4 u = make_uint4(f2tf32(v.x), f2tf32(v.y), f2tf32(v.z), f2tf32(v.w));
            *reinterpret_cast<uint4*>(sw + BUF0 + e * LDB + q * 4) = u;
        }
        __syncthreads();

        // layer 1: H1(buf1) = relu(A(buf0) @ W1 + b1)
        gemm_hidden(sw + BUF0, sw + W1S, TOT, sf + B1S, sw + BUF1, lane, wq);
        __syncthreads();
        // layer 2: H2(buf0) = relu(H1(buf1) @ W2 + b2)
        gemm_hidden(sw + BUF1, sw + W2S, HID, sf + B2S, sw + BUF0, lane, wq);
        __syncthreads();

        // ---- layer 3: D3 = H2 @ W3 (no bias; b3 folded into finalize) ----
        {
            const int mb = (wq & 3) * 16, nb = (wq >> 2) * 24;
            const int r = lane >> 2, c = lane & 3;
            float acc[3][4] = {};
            for (int k = 0; k < HID; k += 8) {
                const u32* ap = sw + BUF0 + (mb + r) * LDB + k + c;
                u32 a[4] = { ap[0], ap[8 * LDB], ap[4], ap[8 * LDB + 4] };
#pragma unroll
                for (int ni = 0; ni < 3; ni++) {
                    const u32* bp = sw + W3S + (k + c) * LDW3 + nb + ni * 8 + r;
                    u32 b[2] = { bp[0], bp[4 * LDW3] };
                    mma_tf32(acc[ni], a, b);
                }
            }
            // stage raw fp32 D3 into buf1 [64][LDD]
#pragma unroll
            for (int ni = 0; ni < 3; ni++) {
                int col = nb + ni * 8 + 2 * c;
                *reinterpret_cast<float2*>(sf + BUF1 + (mb + r) * LDD + col) =
                    make_float2(acc[ni][0], acc[ni][1]);
                *reinterpret_cast<float2*>(sf + BUF1 + (mb + 8 + r) * LDD + col) =
                    make_float2(acc[ni][2], acc[ni][3]);
            }
        }
        __syncthreads();

        // ---- scatter: thread = (row, quarter): 12 contiguous floats = 3 x red.v4 ----
        {
            int row = tid >> 2, q = tid & 3;
            int tgt = sTgt[row];
            if (tgt >= 0) {
                const float* sp = sf + BUF1 + row * LDD + q * 12;
                float* gp = g_msum + (size_t)tgt * N_FEAT + q * 12;
#pragma unroll
                for (int j = 0; j < 3; j++)
                    red_v4(gp + 4 * j, sp[4 * j], sp[4 * j + 1], sp[4 * j + 2], sp[4 * j + 3]);
            }
        }
    }
}

// out = x + (cnt>0 ? msum/cnt + b3 : 0)
__global__ void finalize_kernel(const float* __restrict__ x,
                                const float* __restrict__ b3,
                                float* __restrict__ out) {
    int stride = gridDim.x * blockDim.x;
    for (int i = blockIdx.x * blockDim.x + threadIdx.x; i < N_NODES * N_FEAT; i += stride) {
        int node = i / N_FEAT;
        int col  = i - node * N_FEAT;
        float cnt = (float)g_cnt[node];
        float upd = (cnt > 0.f) ? (g_msum[i] / cnt + b3[col]) : 0.f;
        out[i] = x[i] + upd;
    }
}

extern "C" void kernel_launch(void* const* d_in, const int* in_sizes, int n_in,
                              void* d_out, int out_size) {
    const float* x  = (const float*)d_in[0];
    const int*   ei = (const int*)d_in[1];
    const float* ef = (const float*)d_in[2];
    const float* W1 = (const float*)d_in[3];
    const float* b1 = (const float*)d_in[4];
    const float* W2 = (const float*)d_in[5];
    const float* b2 = (const float*)d_in[6];
    const float* W3 = (const float*)d_in[7];
    const float* b3 = (const float*)d_in[8];
    const int E = in_sizes[2] / N_EFEAT;

    const int smem_bytes = SMEM_WORDS * 4;
    cudaFuncSetAttribute(main_kernel, cudaFuncAttributeMaxDynamicSharedMemorySize, smem_bytes);

    zero_kernel<<<4096, 256>>>();
    main_kernel<<<NCTAS, 256, smem_bytes>>>(x, ei, ef, W1, b1, W2, b2, W3, E);
    finalize_kernel<<<4096, 256>>>(x, b3, (float*)d_out);
}